// round 11
// baseline (speedup 1.0000x reference)
#include <cuda_runtime.h>
#include <cuda_bf16.h>
#include <math_constants.h>

// N=16384 rows, C=1000 classes, 9 matrices (outputs1..8 + mimic).
// Per row/matrix: margin = (x[target] == top1) ? top1 - top2 : 0
// out_threshold = softmax(margins / 2) per row -> d_out[1 + row*9 + m]
// max_preds = max over all elements of matrices 0..7 -> d_out[0]
//
// Fused persistent kernel, contiguous-chunk mapping + pipelined target index:
//  - 9 warps/block, warp m owns matrix m
//  - block b owns rows [b*rpb, b*rpb+rpb): each warp streams ~64KB sequentially
//  - targets[row+1] loaded one iteration ahead -> tv load address ready early
//  - gmax == top1, in-register accumulation, 1 atomic per block
//  - double-buffered s_margin -> one __syncthreads per row
//  - last block finalizes scalar + resets scratch (graph-replay safe)

#define C_DIM  1000
#define CHUNKS 250          // C_DIM / 4 float4 chunks per row
#define BLOCK  288          // 9 warps
#define NEG_INF (-CUDART_INF_F)
#define ENC_NEG_INF 0x007FFFFFu   // enc_f(-inf)

struct Ptrs { const float* p[9]; };

__device__ unsigned g_max_enc = ENC_NEG_INF;
__device__ unsigned g_done    = 0u;

__device__ __forceinline__ unsigned enc_f(float x) {
    unsigned u = __float_as_uint(x);
    return (u & 0x80000000u) ? ~u : (u | 0x80000000u);
}
__device__ __forceinline__ float dec_f(unsigned e) {
    return (e & 0x80000000u) ? __uint_as_float(e ^ 0x80000000u)
                             : __uint_as_float(~e);
}

// accumulate top-2 of a float4 into (t1, t2)
__device__ __forceinline__ void acc4(float4 v, float& t1, float& t2) {
    float hi1 = fmaxf(v.x, v.y), lo1 = fminf(v.x, v.y);
    float hi2 = fmaxf(v.z, v.w), lo2 = fminf(v.z, v.w);
    float m1 = fmaxf(hi1, hi2);
    float m2 = fmaxf(fminf(hi1, hi2), (hi1 >= hi2) ? lo1 : lo2);
    t2 = fmaxf(fminf(t1, m1), fmaxf(t2, m2));
    t1 = fmaxf(t1, m1);
}

__device__ __forceinline__ long long load_tg(const unsigned* t32, int row,
                                             unsigned is32) {
    if (is32) return (long long)((const int*)t32)[row];
    return ((const long long*)t32)[row];
}

__global__ __launch_bounds__(BLOCK, 6)
void margin_softmax_kernel(Ptrs ptrs, const unsigned* __restrict__ t32,
                           float* __restrict__ out, int nrows, int rpb) {
    const int t    = threadIdx.x;
    const int lane = t & 31;
    const int w    = t >> 5;          // warp index == matrix index 0..8

    __shared__ float s_margin[2][12]; // double-buffered, padded
    __shared__ float s_gm[8];

    // targets dtype detect, once: int64 values < 1000 => all odd words 0
    unsigned odd  = t32[2 * lane + 1];
    unsigned is32 = __reduce_or_sync(0xFFFFFFFFu, odd);

    const int row0   = blockIdx.x * rpb;
    const int rowEnd = min(row0 + rpb, nrows);

    const float* base = ptrs.p[w];
    float gm = NEG_INF;               // per-warp running max (lane 0 authoritative)

    // pipelined target index: tg holds the index for the CURRENT row
    long long tg = (row0 < rowEnd) ? load_tg(t32, row0, is32) : 0;

    int it = 0;
    for (int row = row0; row < rowEnd; ++row, ++it) {
        // issue next row's target load immediately (hides the tg->tv chain)
        long long tg_next = (row + 1 < rowEnd) ? load_tg(t32, row + 1, is32) : 0;

        const float* rowp = base + (size_t)row * C_DIM;
        const float4* rp4 = reinterpret_cast<const float4*>(rowp);

        float tv = rowp[tg];          // address ready since last iteration

        // wave A: chunks lane + {0,32,64,96}
        float4 va0 = rp4[lane];
        float4 va1 = rp4[lane + 32];
        float4 va2 = rp4[lane + 64];
        float4 va3 = rp4[lane + 96];
        float t1 = NEG_INF, t2 = NEG_INF;
        acc4(va0, t1, t2);
        acc4(va1, t1, t2);
        acc4(va2, t1, t2);
        acc4(va3, t1, t2);

        // wave B: chunks lane + {128,160,192,224} (last predicated)
        float4 vb0 = rp4[lane + 128];
        float4 vb1 = rp4[lane + 160];
        float4 vb2 = rp4[lane + 192];
        float4 vb3 = (lane + 224 < CHUNKS) ? rp4[lane + 224]
                   : make_float4(NEG_INF, NEG_INF, NEG_INF, NEG_INF);
        acc4(vb0, t1, t2);
        acc4(vb1, t1, t2);
        acc4(vb2, t1, t2);
        acc4(vb3, t1, t2);

        // warp top-2 reduction
#pragma unroll
        for (int off = 16; off > 0; off >>= 1) {
            float o1 = __shfl_down_sync(0xFFFFFFFFu, t1, off);
            float o2 = __shfl_down_sync(0xFFFFFFFFu, t2, off);
            t2 = fmaxf(fminf(t1, o1), fmaxf(t2, o2));
            t1 = fmaxf(t1, o1);
        }
        if (lane == 0) {
            s_margin[it & 1][w] = (tv == t1) ? (t1 - t2) : 0.0f;
            gm = fmaxf(gm, t1);       // row max == top1
        }
        __syncthreads();

        if (w == 0) {
            // softmax over 9 margins / T=2, lanes 0..8 (16-lane butterfly)
            float m = (lane < 9) ? s_margin[it & 1][lane] : NEG_INF;
            float mm = m;
#pragma unroll
            for (int off = 8; off > 0; off >>= 1)
                mm = fmaxf(mm, __shfl_xor_sync(0xFFFFFFFFu, mm, off, 16));
            float e = __expf((m - mm) * 0.5f);
            float sum = e;
#pragma unroll
            for (int off = 8; off > 0; off >>= 1)
                sum += __shfl_xor_sync(0xFFFFFFFFu, sum, off, 16);
            if (lane < 9)
                out[1 + (size_t)row * 9 + lane] = __fdividef(e, sum);
        }
        tg = tg_next;
        // s_margin WAR across iterations is protected by double buffering:
        // buffer (it&1) is rewritten only after two more barriers.
    }

    // block-level scalar max: one shared write per warp, one atomic per block
    if (lane == 0 && w < 8) s_gm[w] = gm;
    __syncthreads();
    if (t == 0) {
        float g = s_gm[0];
#pragma unroll
        for (int i = 1; i < 8; i++) g = fmaxf(g, s_gm[i]);
        atomicMax(&g_max_enc, enc_f(g));
        __threadfence();
        unsigned done = atomicAdd(&g_done, 1u);
        if (done == gridDim.x - 1) {
            __threadfence();
            unsigned cur = atomicOr(&g_max_enc, 0u);   // atomic read
            out[0] = dec_f(cur);
            // reset scratch for next graph replay
            g_max_enc = ENC_NEG_INF;
            g_done    = 0u;
        }
    }
}

extern "C" void kernel_launch(void* const* d_in, const int* in_sizes, int n_in,
                              void* d_out, int out_size) {
    Ptrs ps;
    for (int i = 0; i < 9; i++) ps.p[i] = (const float*)d_in[i];
    const unsigned* targets = (const unsigned*)d_in[9];
    float* out = (float*)d_out;

    const int N = in_sizes[9];   // 16384 rows

    int grid = 1024;             // 16 contiguous rows per block for N=16384
    if (grid > N) grid = N;
    int rpb = (N + grid - 1) / grid;

    margin_softmax_kernel<<<grid, BLOCK>>>(ps, targets, out, N, rpb);
}

// round 12
// speedup vs baseline: 1.1075x; 1.1075x over previous
#include <cuda_runtime.h>
#include <cuda_bf16.h>
#include <math_constants.h>

// N=16384 rows, C=1000 classes, 9 matrices (outputs1..8 + mimic).
// Per row/matrix: margin = (x[target] == top1) ? top1 - top2 : 0
// out_threshold = softmax(margins / 2) per row -> d_out[1 + row*9 + m]
// max_preds = max over all elements of matrices 0..7 -> d_out[0]
//
// R7 design (best: 98.3us) + streaming cache hints (__ldcs) on the one-touch
// payload loads. Grid-stride row mapping (interleaved rows across blocks beat
// contiguous chunks by ~5% DRAM util in R10's A/B).
//  - 9 warps/block, warp m owns matrix m; grid = SMs*6 (912 on GB300)
//  - gmax == top1, in-register accumulation, 1 atomic per block
//  - double-buffered s_margin -> one __syncthreads per row
//  - last block finalizes scalar + resets scratch (graph-replay safe)

#define C_DIM  1000
#define CHUNKS 250          // C_DIM / 4 float4 chunks per row
#define BLOCK  288          // 9 warps
#define NEG_INF (-CUDART_INF_F)
#define ENC_NEG_INF 0x007FFFFFu   // enc_f(-inf)

struct Ptrs { const float* p[9]; };

__device__ unsigned g_max_enc = ENC_NEG_INF;
__device__ unsigned g_done    = 0u;

__device__ __forceinline__ unsigned enc_f(float x) {
    unsigned u = __float_as_uint(x);
    return (u & 0x80000000u) ? ~u : (u | 0x80000000u);
}
__device__ __forceinline__ float dec_f(unsigned e) {
    return (e & 0x80000000u) ? __uint_as_float(e ^ 0x80000000u)
                             : __uint_as_float(~e);
}

// accumulate top-2 of a float4 into (t1, t2)
__device__ __forceinline__ void acc4(float4 v, float& t1, float& t2) {
    float hi1 = fmaxf(v.x, v.y), lo1 = fminf(v.x, v.y);
    float hi2 = fmaxf(v.z, v.w), lo2 = fminf(v.z, v.w);
    float m1 = fmaxf(hi1, hi2);
    float m2 = fmaxf(fminf(hi1, hi2), (hi1 >= hi2) ? lo1 : lo2);
    t2 = fmaxf(fminf(t1, m1), fmaxf(t2, m2));
    t1 = fmaxf(t1, m1);
}

__global__ __launch_bounds__(BLOCK, 6)
void margin_softmax_kernel(Ptrs ptrs, const unsigned* __restrict__ t32,
                           float* __restrict__ out, int nrows) {
    const int t    = threadIdx.x;
    const int lane = t & 31;
    const int w    = t >> 5;          // warp index == matrix index 0..8

    __shared__ float s_margin[2][12]; // double-buffered, padded
    __shared__ float s_gm[8];

    // targets dtype detect, once: int64 values < 1000 => all odd words 0
    unsigned odd  = __ldg(&t32[2 * lane + 1]);
    unsigned is32 = __reduce_or_sync(0xFFFFFFFFu, odd);

    const float* base = ptrs.p[w];
    float gm = NEG_INF;               // per-warp running max (lane 0 authoritative)

    int it = 0;
    for (int row = blockIdx.x; row < nrows; row += gridDim.x, ++it) {
        long long tg;
        if (is32) tg = (long long)__ldg(&((const int*)t32)[row]);
        else      tg = __ldg(&((const long long*)t32)[row]);

        const float* rowp = base + (size_t)row * C_DIM;
        const float4* rp4 = reinterpret_cast<const float4*>(rowp);

        float tv = __ldg(&rowp[tg]);  // broadcast load (uniform in warp)

        // wave A: chunks lane + {0,32,64,96}  -- streaming (one-touch) loads
        float4 va0 = __ldcs(&rp4[lane]);
        float4 va1 = __ldcs(&rp4[lane + 32]);
        float4 va2 = __ldcs(&rp4[lane + 64]);
        float4 va3 = __ldcs(&rp4[lane + 96]);
        float t1 = NEG_INF, t2 = NEG_INF;
        acc4(va0, t1, t2);
        acc4(va1, t1, t2);
        acc4(va2, t1, t2);
        acc4(va3, t1, t2);

        // wave B: chunks lane + {128,160,192,224} (last predicated)
        float4 vb0 = __ldcs(&rp4[lane + 128]);
        float4 vb1 = __ldcs(&rp4[lane + 160]);
        float4 vb2 = __ldcs(&rp4[lane + 192]);
        float4 vb3 = (lane + 224 < CHUNKS) ? __ldcs(&rp4[lane + 224])
                   : make_float4(NEG_INF, NEG_INF, NEG_INF, NEG_INF);
        acc4(vb0, t1, t2);
        acc4(vb1, t1, t2);
        acc4(vb2, t1, t2);
        acc4(vb3, t1, t2);

        // warp top-2 reduction
#pragma unroll
        for (int off = 16; off > 0; off >>= 1) {
            float o1 = __shfl_down_sync(0xFFFFFFFFu, t1, off);
            float o2 = __shfl_down_sync(0xFFFFFFFFu, t2, off);
            t2 = fmaxf(fminf(t1, o1), fmaxf(t2, o2));
            t1 = fmaxf(t1, o1);
        }
        if (lane == 0) {
            s_margin[it & 1][w] = (tv == t1) ? (t1 - t2) : 0.0f;
            gm = fmaxf(gm, t1);       // row max == top1
        }
        __syncthreads();

        if (w == 0) {
            // softmax over 9 margins / T=2, lanes 0..8 (16-lane butterfly)
            float m = (lane < 9) ? s_margin[it & 1][lane] : NEG_INF;
            float mm = m;
#pragma unroll
            for (int off = 8; off > 0; off >>= 1)
                mm = fmaxf(mm, __shfl_xor_sync(0xFFFFFFFFu, mm, off, 16));
            float e = __expf((m - mm) * 0.5f);
            float sum = e;
#pragma unroll
            for (int off = 8; off > 0; off >>= 1)
                sum += __shfl_xor_sync(0xFFFFFFFFu, sum, off, 16);
            if (lane < 9)
                out[1 + (size_t)row * 9 + lane] = __fdividef(e, sum);
        }
        // s_margin WAR across iterations is protected by double buffering:
        // buffer (it&1) is rewritten only after two more barriers.
    }

    // block-level scalar max: one shared write per warp, one atomic per block
    if (lane == 0 && w < 8) s_gm[w] = gm;
    __syncthreads();
    if (t == 0) {
        float g = s_gm[0];
#pragma unroll
        for (int i = 1; i < 8; i++) g = fmaxf(g, s_gm[i]);
        atomicMax(&g_max_enc, enc_f(g));
        __threadfence();
        unsigned done = atomicAdd(&g_done, 1u);
        if (done == gridDim.x - 1) {
            __threadfence();
            unsigned cur = atomicOr(&g_max_enc, 0u);   // atomic read
            out[0] = dec_f(cur);
            // reset scratch for next graph replay
            g_max_enc = ENC_NEG_INF;
            g_done    = 0u;
        }
    }
}

extern "C" void kernel_launch(void* const* d_in, const int* in_sizes, int n_in,
                              void* d_out, int out_size) {
    Ptrs ps;
    for (int i = 0; i < 9; i++) ps.p[i] = (const float*)d_in[i];
    const unsigned* targets = (const unsigned*)d_in[9];
    float* out = (float*)d_out;

    const int N = in_sizes[9];   // 16384 rows

    int sms = 148;
    cudaDeviceGetAttribute(&sms, cudaDevAttrMultiProcessorCount, 0);
    int grid = sms * 6;          // 912 on GB300 (152 SMs)
    if (grid > N) grid = N;

    margin_softmax_kernel<<<grid, BLOCK>>>(ps, targets, out, N);
}

// round 13
// speedup vs baseline: 1.1385x; 1.0280x over previous
#include <cuda_runtime.h>
#include <cuda_bf16.h>
#include <math_constants.h>

// N=16384 rows, C=1000 classes, 9 matrices (outputs1..8 + mimic).
// Per row/matrix: margin = (x[target] == top1) ? top1 - top2 : 0
// out_threshold = softmax(margins / 2) per row -> d_out[1 + row*9 + m]
// max_preds = max over all elements of matrices 0..7 -> d_out[0]
//
// R11 design (95.3us) + row-PAIR per iteration:
//  - 9 warps/block, warp m owns matrix m; grid-stride over row pairs
//  - 16 x 128B streaming loads per barrier (was 8) -> fewer block-wide
//    no-load bubbles; barriers/softmax epilogues halved
//  - __ldcs on one-touch payload, __ldg on targets/tv
//  - gmax == top1, in-register accumulation, 1 atomic per block
//  - double-buffered s_margin -> one __syncthreads per pair
//  - last block finalizes scalar + resets scratch (graph-replay safe)

#define C_DIM  1000
#define CHUNKS 250          // C_DIM / 4 float4 chunks per row
#define BLOCK  288          // 9 warps
#define NEG_INF (-CUDART_INF_F)
#define ENC_NEG_INF 0x007FFFFFu   // enc_f(-inf)

struct Ptrs { const float* p[9]; };

__device__ unsigned g_max_enc = ENC_NEG_INF;
__device__ unsigned g_done    = 0u;

__device__ __forceinline__ unsigned enc_f(float x) {
    unsigned u = __float_as_uint(x);
    return (u & 0x80000000u) ? ~u : (u | 0x80000000u);
}
__device__ __forceinline__ float dec_f(unsigned e) {
    return (e & 0x80000000u) ? __uint_as_float(e ^ 0x80000000u)
                             : __uint_as_float(~e);
}

// accumulate top-2 of a float4 into (t1, t2)
__device__ __forceinline__ void acc4(float4 v, float& t1, float& t2) {
    float hi1 = fmaxf(v.x, v.y), lo1 = fminf(v.x, v.y);
    float hi2 = fmaxf(v.z, v.w), lo2 = fminf(v.z, v.w);
    float m1 = fmaxf(hi1, hi2);
    float m2 = fmaxf(fminf(hi1, hi2), (hi1 >= hi2) ? lo1 : lo2);
    t2 = fmaxf(fminf(t1, m1), fmaxf(t2, m2));
    t1 = fmaxf(t1, m1);
}

__global__ __launch_bounds__(BLOCK, 5)
void margin_softmax_kernel(Ptrs ptrs, const unsigned* __restrict__ t32,
                           float* __restrict__ out, int nrows) {
    const int t    = threadIdx.x;
    const int lane = t & 31;
    const int w    = t >> 5;          // warp index == matrix index 0..8

    __shared__ float s_margin[2][2][12]; // [buf][row-in-pair][warp], padded
    __shared__ float s_gm[8];

    // targets dtype detect, once: int64 values < 1000 => all odd words 0
    unsigned odd  = __ldg(&t32[2 * lane + 1]);
    unsigned is32 = __reduce_or_sync(0xFFFFFFFFu, odd);

    const float* base = ptrs.p[w];
    float gm = NEG_INF;               // per-warp running max (lane 0 authoritative)

    const int npairs = (nrows + 1) >> 1;
    int it = 0;
    for (int p = blockIdx.x; p < npairs; p += gridDim.x, ++it) {
        const int row0 = 2 * p;
        const int row1 = row0 + 1;    // nrows is even (16384); kept general below

        long long tg0, tg1;
        if (is32) {
            tg0 = (long long)__ldg(&((const int*)t32)[row0]);
            tg1 = (long long)__ldg(&((const int*)t32)[row1]);
        } else {
            tg0 = __ldg(&((const long long*)t32)[row0]);
            tg1 = __ldg(&((const long long*)t32)[row1]);
        }

        const float* rowp0 = base + (size_t)row0 * C_DIM;
        const float* rowp1 = rowp0 + C_DIM;
        const float4* r0 = reinterpret_cast<const float4*>(rowp0);
        const float4* r1 = reinterpret_cast<const float4*>(rowp1);

        float tv0 = __ldg(&rowp0[tg0]);
        float tv1 = __ldg(&rowp1[tg1]);

        // wave A: both rows, chunks lane + {0,32,64,96} -> 8 loads in flight
        float4 a00 = __ldcs(&r0[lane]);
        float4 a01 = __ldcs(&r0[lane + 32]);
        float4 a02 = __ldcs(&r0[lane + 64]);
        float4 a03 = __ldcs(&r0[lane + 96]);
        float4 a10 = __ldcs(&r1[lane]);
        float4 a11 = __ldcs(&r1[lane + 32]);
        float4 a12 = __ldcs(&r1[lane + 64]);
        float4 a13 = __ldcs(&r1[lane + 96]);

        float t1a = NEG_INF, t2a = NEG_INF;   // row0 top-2
        float t1b = NEG_INF, t2b = NEG_INF;   // row1 top-2
        acc4(a00, t1a, t2a); acc4(a10, t1b, t2b);
        acc4(a01, t1a, t2a); acc4(a11, t1b, t2b);
        acc4(a02, t1a, t2a); acc4(a12, t1b, t2b);
        acc4(a03, t1a, t2a); acc4(a13, t1b, t2b);

        // wave B: both rows, chunks lane + {128,160,192,224} (last predicated)
        float4 nf = make_float4(NEG_INF, NEG_INF, NEG_INF, NEG_INF);
        float4 b00 = __ldcs(&r0[lane + 128]);
        float4 b01 = __ldcs(&r0[lane + 160]);
        float4 b02 = __ldcs(&r0[lane + 192]);
        float4 b03 = (lane + 224 < CHUNKS) ? __ldcs(&r0[lane + 224]) : nf;
        float4 b10 = __ldcs(&r1[lane + 128]);
        float4 b11 = __ldcs(&r1[lane + 160]);
        float4 b12 = __ldcs(&r1[lane + 192]);
        float4 b13 = (lane + 224 < CHUNKS) ? __ldcs(&r1[lane + 224]) : nf;

        acc4(b00, t1a, t2a); acc4(b10, t1b, t2b);
        acc4(b01, t1a, t2a); acc4(b11, t1b, t2b);
        acc4(b02, t1a, t2a); acc4(b12, t1b, t2b);
        acc4(b03, t1a, t2a); acc4(b13, t1b, t2b);

        // warp top-2 reduction, 4 streams in one loop
#pragma unroll
        for (int off = 16; off > 0; off >>= 1) {
            float o1a = __shfl_down_sync(0xFFFFFFFFu, t1a, off);
            float o2a = __shfl_down_sync(0xFFFFFFFFu, t2a, off);
            float o1b = __shfl_down_sync(0xFFFFFFFFu, t1b, off);
            float o2b = __shfl_down_sync(0xFFFFFFFFu, t2b, off);
            t2a = fmaxf(fminf(t1a, o1a), fmaxf(t2a, o2a));
            t1a = fmaxf(t1a, o1a);
            t2b = fmaxf(fminf(t1b, o1b), fmaxf(t2b, o2b));
            t1b = fmaxf(t1b, o1b);
        }
        if (lane == 0) {
            s_margin[it & 1][0][w] = (tv0 == t1a) ? (t1a - t2a) : 0.0f;
            s_margin[it & 1][1][w] = (tv1 == t1b) ? (t1b - t2b) : 0.0f;
            gm = fmaxf(gm, fmaxf(t1a, t1b));    // row max == top1
        }
        __syncthreads();

        if (w == 0) {
            // two softmaxes in one warp: lanes 0..8 -> row0, 16..24 -> row1
            int half = lane >> 4;      // 0 or 1
            int l16  = lane & 15;
            float m = (l16 < 9) ? s_margin[it & 1][half][l16] : NEG_INF;
            float mm = m;
#pragma unroll
            for (int off = 8; off > 0; off >>= 1)
                mm = fmaxf(mm, __shfl_xor_sync(0xFFFFFFFFu, mm, off, 16));
            float e = __expf((m - mm) * 0.5f);
            float sum = e;
#pragma unroll
            for (int off = 8; off > 0; off >>= 1)
                sum += __shfl_xor_sync(0xFFFFFFFFu, sum, off, 16);
            int row = row0 + half;
            if (l16 < 9 && row < nrows)
                out[1 + (size_t)row * 9 + l16] = __fdividef(e, sum);
        }
        // s_margin WAR across iterations protected by double buffering.
    }

    // block-level scalar max: one shared write per warp, one atomic per block
    if (lane == 0 && w < 8) s_gm[w] = gm;
    __syncthreads();
    if (t == 0) {
        float g = s_gm[0];
#pragma unroll
        for (int i = 1; i < 8; i++) g = fmaxf(g, s_gm[i]);
        atomicMax(&g_max_enc, enc_f(g));
        __threadfence();
        unsigned done = atomicAdd(&g_done, 1u);
        if (done == gridDim.x - 1) {
            __threadfence();
            unsigned cur = atomicOr(&g_max_enc, 0u);   // atomic read
            out[0] = dec_f(cur);
            // reset scratch for next graph replay
            g_max_enc = ENC_NEG_INF;
            g_done    = 0u;
        }
    }
}

extern "C" void kernel_launch(void* const* d_in, const int* in_sizes, int n_in,
                              void* d_out, int out_size) {
    Ptrs ps;
    for (int i = 0; i < 9; i++) ps.p[i] = (const float*)d_in[i];
    const unsigned* targets = (const unsigned*)d_in[9];
    float* out = (float*)d_out;

    const int N = in_sizes[9];   // 16384 rows
    const int npairs = (N + 1) / 2;

    int sms = 148;
    cudaDeviceGetAttribute(&sms, cudaDevAttrMultiProcessorCount, 0);
    int grid = sms * 5;          // match __launch_bounds__(288, 5)
    if (grid > npairs) grid = npairs;

    margin_softmax_kernel<<<grid, BLOCK>>>(ps, targets, out, N);
}